// round 15
// baseline (speedup 1.0000x reference)
#include <cuda_runtime.h>
#include <cuda_fp16.h>
#include <cuda.h>
#include <cstdint>

// out[b,h,o] = sum_d gathered[b,h,d] * W[h,o,d] + bias[h,o]
// gathered[b,h, 64*k + w] = x[b, mask[h,k], w]
// x:(512,128,64) f32, mask:(256,4) i32 (declared i64; JAX x64-off),
// W:(256,64,256) f32, b:(256,64) f32, out:(512,256,64) f32.
//
// 1) split: x, W -> fp16 scratch.
// 2) gemm: BM=64, 4 warps m32xn32. Deep TMA prefetch: A 3-stage, W 2-stage,
//    only TWO __syncthreads in the whole mainloop; chunks 2-3 barrier-free.
//    Single-pass fp16 mma.sync m16n8k16, fp32 accum (~2.9e-4 rel err).

namespace asl {

constexpr int B_SZ = 512, H_IN = 128, W_IN = 64, H_OUT = 256, W_OUT = 64;
constexpr int KSEL = 4, D = 256;
constexpr int BM = 64;           // batch rows per CTA
constexpr int THREADS = 128;     // 4 warps, warp tile m32 x n32

// fp16 scratch, pair-packed.
__device__ alignas(1024) uint32_t g_xhi[B_SZ * H_IN * W_IN / 2];
__device__ alignas(1024) uint32_t g_whi[H_OUT * W_OUT * D / 2];

// ---------------- split kernel ----------------
__device__ __forceinline__ uint2 cvt4(float4 v) {
    __half2 h0 = __floats2half2_rn(v.x, v.y);
    __half2 h1 = __floats2half2_rn(v.z, v.w);
    uint2 r;
    r.x = *reinterpret_cast<uint32_t*>(&h0);
    r.y = *reinterpret_cast<uint32_t*>(&h1);
    return r;
}

__global__ void split_kernel(const float4* __restrict__ x,
                             const float4* __restrict__ w) {
    constexpr int XQ = B_SZ * H_IN * W_IN / 4;
    constexpr int WQ = H_OUT * W_OUT * D / 4;
    int i = blockIdx.x * blockDim.x + threadIdx.x;
    int stride = gridDim.x * blockDim.x;
    for (; i < XQ + WQ; i += stride) {
        if (i < XQ)
            reinterpret_cast<uint2*>(g_xhi)[i] = cvt4(x[i]);
        else
            reinterpret_cast<uint2*>(g_whi)[i - XQ] = cvt4(w[i - XQ]);
    }
}

// ---------------- helpers ----------------
__device__ __forceinline__ bool mask_is_i64(const int* m32) {
    int acc = 0;
#pragma unroll
    for (int i = 0; i < 16; ++i) acc |= m32[2 * i + 1];
    return acc == 0;
}
__device__ __forceinline__ int mask_val(const int* m32, bool is64, int idx) {
    int v = is64 ? m32[2 * idx] : m32[idx];
    return min(max(v, 0), H_IN - 1);
}
__device__ __forceinline__ void mma16816(float* c, const uint32_t* a, const uint32_t* b) {
    asm volatile(
        "mma.sync.aligned.m16n8k16.row.col.f32.f16.f16.f32 "
        "{%0,%1,%2,%3}, {%4,%5,%6,%7}, {%8,%9}, {%0,%1,%2,%3};"
        : "+f"(c[0]), "+f"(c[1]), "+f"(c[2]), "+f"(c[3])
        : "r"(a[0]), "r"(a[1]), "r"(a[2]), "r"(a[3]), "r"(b[0]), "r"(b[1]));
}
__device__ __forceinline__ void ldsm4(uint32_t* r, uint32_t saddr) {
    asm volatile("ldmatrix.sync.aligned.m8n8.x4.shared.b16 {%0,%1,%2,%3}, [%4];"
                 : "=r"(r[0]), "=r"(r[1]), "=r"(r[2]), "=r"(r[3]) : "r"(saddr));
}
__device__ __forceinline__ uint32_t smem_u32(const void* p) {
    uint32_t a;
    asm("{ .reg .u64 t; cvta.to.shared.u64 t, %1; cvt.u32.u64 %0, t; }" : "=r"(a) : "l"(p));
    return a;
}
__device__ __forceinline__ void mbar_init(uint32_t m, uint32_t cnt) {
    asm volatile("mbarrier.init.shared.b64 [%0], %1;" :: "r"(m), "r"(cnt) : "memory");
}
__device__ __forceinline__ void mbar_expect_tx(uint32_t m, uint32_t bytes) {
    asm volatile("mbarrier.arrive.expect_tx.shared.b64 _, [%0], %1;"
                 :: "r"(m), "r"(bytes) : "memory");
}
__device__ __forceinline__ void mbar_wait(uint32_t m, uint32_t parity) {
    asm volatile(
        "{ .reg .pred P;\n"
        "W_%=:\n"
        " mbarrier.try_wait.parity.acquire.cta.shared::cta.b64 P, [%0], %1, 0x989680;\n"
        " @P bra D_%=;\n"
        " bra W_%=;\n"
        "D_%=:\n}"
        :: "r"(m), "r"(parity) : "memory");
}
__device__ __forceinline__ void tma3(uint32_t smem, const CUtensorMap* m,
                                     int c0, int c1, int c2, uint32_t mbar) {
    asm volatile(
        "cp.async.bulk.tensor.3d.shared::cta.global.tile.mbarrier::complete_tx::bytes "
        "[%0], [%1, {%2, %3, %4}], [%5];"
        :: "r"(smem), "l"(m), "r"(c0), "r"(c1), "r"(c2), "r"(mbar) : "memory");
}
__device__ __forceinline__ void tma2(uint32_t smem, const CUtensorMap* m,
                                     int c0, int c1, uint32_t mbar) {
    asm volatile(
        "cp.async.bulk.tensor.2d.shared::cta.global.tile.mbarrier::complete_tx::bytes "
        "[%0], [%1, {%2, %3}], [%4];"
        :: "r"(smem), "l"(m), "r"(c0), "r"(c1), "r"(mbar) : "memory");
}

// ---------------- gemm kernel ----------------
__global__ __launch_bounds__(THREADS)
void gemm_kernel(const __grid_constant__ CUtensorMap mapA,
                 const __grid_constant__ CUtensorMap mapW,
                 const int* __restrict__ mask32,
                 const float* __restrict__ bias,
                 float* __restrict__ out) {
    // A: 3 stages x 8KB, W: 2 stages x 8KB -> 40KB static.
    __shared__ alignas(1024) uint32_t sA[3][BM * 32];
    __shared__ alignas(1024) uint32_t sW[2][W_OUT * 32];
    __shared__ alignas(8) uint64_t s_mbA[3];
    __shared__ alignas(8) uint64_t s_mbW[2];

    const int h  = blockIdx.y;
    const int b0 = blockIdx.x * BM;
    const int t    = threadIdx.x;
    const int wid  = t >> 5;
    const int lane = t & 31;
    const int g  = lane >> 2;
    const int tq = lane & 3;
    const int wm = wid & 1;
    const int wn = wid >> 1;

    const bool m64flag = mask_is_i64(mask32);
    int xrows[KSEL];
#pragma unroll
    for (int k = 0; k < KSEL; ++k) xrows[k] = mask_val(mask32, m64flag, h * KSEL + k);

    uint32_t aS[3] = {smem_u32(sA[0]), smem_u32(sA[1]), smem_u32(sA[2])};
    uint32_t wS[2] = {smem_u32(sW[0]), smem_u32(sW[1])};
    uint32_t mbA[3] = {smem_u32(&s_mbA[0]), smem_u32(&s_mbA[1]), smem_u32(&s_mbA[2])};
    uint32_t mbW[2] = {smem_u32(&s_mbW[0]), smem_u32(&s_mbW[1])};

    if (t == 0) {
#pragma unroll
        for (int i = 0; i < 3; ++i) mbar_init(mbA[i], 1);
#pragma unroll
        for (int i = 0; i < 2; ++i) mbar_init(mbW[i], 1);
    }
    __syncthreads();

    // prologue: A chunks 0..2, W chunks 0..1
    if (t == 0) {
        mbar_expect_tx(mbA[0], 8192);
        tma3(aS[0], &mapA, 0, xrows[0], b0, mbA[0]);
        mbar_expect_tx(mbA[1], 8192);
        tma3(aS[1], &mapA, 0, xrows[1], b0, mbA[1]);
        mbar_expect_tx(mbA[2], 8192);
        tma3(aS[2], &mapA, 0, xrows[2], b0, mbA[2]);
        mbar_expect_tx(mbW[0], 8192);
        tma2(wS[0], &mapW, 0, h * W_OUT, mbW[0]);
        mbar_expect_tx(mbW[1], 8192);
        tma2(wS[1], &mapW, 64, h * W_OUT, mbW[1]);
    }

    // bias prefetch (registers), before any waiting
    float bx[4], by[4];
#pragma unroll
    for (int nf = 0; nf < 4; ++nf) {
        int col = wn * 32 + nf * 8 + tq * 2;
        bx[nf] = __ldg(bias + h * W_OUT + col);
        by[nf] = __ldg(bias + h * W_OUT + col + 1);
    }

    // ldmatrix lane geometry (row offsets are multiples of 8 -> swizzle XOR
    // term is the constant lane&7).
    const int rx   = lane & 7;
    const int a_hi = lane >> 4;
    const int b_hi = (lane >> 3) & 1;
    uint32_t aRow[2], bRow[2];
#pragma unroll
    for (int mf = 0; mf < 2; ++mf)
        aRow[mf] = (uint32_t)((wm * 32 + mf * 16 + (lane & 15)) * 128);
#pragma unroll
    for (int pr = 0; pr < 2; ++pr)
        bRow[pr] = (uint32_t)((wn * 32 + pr * 16 + (lane & 7) + ((lane >> 4) << 3)) * 128);

    float acc[2][4][4];
#pragma unroll
    for (int a = 0; a < 2; ++a)
#pragma unroll
        for (int b = 0; b < 4; ++b)
#pragma unroll
            for (int c = 0; c < 4; ++c) acc[a][b][c] = 0.0f;

    auto compute_chunk = [&](uint32_t aBase, uint32_t wBase) {
#pragma unroll
        for (int ks = 0; ks < 4; ++ks) {
            uint32_t ah[8], bh[8];
            const int ks2 = ks * 2;
            const uint32_t akOff = (uint32_t)(((ks2 + a_hi) ^ rx) << 4);
            const uint32_t bkOff = (uint32_t)(((ks2 + b_hi) ^ rx) << 4);
#pragma unroll
            for (int mf = 0; mf < 2; ++mf)
                ldsm4(&ah[mf * 4], aBase + aRow[mf] + akOff);
#pragma unroll
            for (int pr = 0; pr < 2; ++pr)
                ldsm4(&bh[pr * 4], wBase + bRow[pr] + bkOff);
#pragma unroll
            for (int mf = 0; mf < 2; ++mf)
#pragma unroll
                for (int nf = 0; nf < 4; ++nf)
                    mma16816(acc[mf][nf], &ah[mf * 4], &bh[nf * 2]);
        }
    };

    // ---- chunk 0 ----
    mbar_wait(mbA[0], 0);
    mbar_wait(mbW[0], 0);
    compute_chunk(aS[0], wS[0]);
    __syncthreads();                       // release sA[0], sW[0]
    if (t == 0) {
        mbar_expect_tx(mbA[0], 8192);
        tma3(aS[0], &mapA, 0, xrows[3], b0, mbA[0]);   // A3 -> stage 0
        mbar_expect_tx(mbW[0], 8192);
        tma2(wS[0], &mapW, 128, h * W_OUT, mbW[0]);    // W2 -> stage 0
    }

    // ---- chunk 1 ----
    mbar_wait(mbA[1], 0);
    mbar_wait(mbW[1], 0);
    compute_chunk(aS[1], wS[1]);
    __syncthreads();                       // release sW[1]
    if (t == 0) {
        mbar_expect_tx(mbW[1], 8192);
        tma2(wS[1], &mapW, 192, h * W_OUT, mbW[1]);    // W3 -> stage 1
    }

    // ---- chunk 2 (no barrier before or after) ----
    mbar_wait(mbA[2], 0);
    mbar_wait(mbW[0], 1);
    compute_chunk(aS[2], wS[0]);

    // ---- chunk 3 (flows straight from chunk 2) ----
    mbar_wait(mbA[0], 1);
    mbar_wait(mbW[1], 1);
    compute_chunk(aS[0], wS[1]);

    // ---- epilogue: add bias, float2 stores ----
#pragma unroll
    for (int nf = 0; nf < 4; ++nf) {
        int col = wn * 32 + nf * 8 + tq * 2;
#pragma unroll
        for (int mf = 0; mf < 2; ++mf) {
            int row0 = b0 + wm * 32 + mf * 16 + g;
            float2 v0 = {acc[mf][nf][0] + bx[nf], acc[mf][nf][1] + by[nf]};
            float2 v1 = {acc[mf][nf][2] + bx[nf], acc[mf][nf][3] + by[nf]};
            *reinterpret_cast<float2*>(
                out + ((size_t)row0 * H_OUT + h) * W_OUT + col) = v0;
            *reinterpret_cast<float2*>(
                out + ((size_t)(row0 + 8) * H_OUT + h) * W_OUT + col) = v1;
        }
    }
}

} // namespace asl

// ---------------- host ----------------
typedef CUresult (*EncodeTiledFn)(
    CUtensorMap*, CUtensorMapDataType, cuuint32_t, void*,
    const cuuint64_t*, const cuuint64_t*, const cuuint32_t*, const cuuint32_t*,
    CUtensorMapInterleave, CUtensorMapSwizzle, CUtensorMapL2promotion,
    CUtensorMapFloatOOBfill);

extern "C" void kernel_launch(void* const* d_in, const int* in_sizes, int n_in,
                              void* d_out, int out_size) {
    const float* x      = (const float*)d_in[0];
    const int*   mask32 = (const int*)d_in[1];
    const float* W      = (const float*)d_in[2];
    const float* bias   = (const float*)d_in[3];
    float*       out    = (float*)d_out;

    asl::split_kernel<<<2048, 256>>>(
        reinterpret_cast<const float4*>(x), reinterpret_cast<const float4*>(W));

    void* xhi = nullptr; void* whi = nullptr;
    cudaGetSymbolAddress(&xhi, asl::g_xhi);
    cudaGetSymbolAddress(&whi, asl::g_whi);

    EncodeTiledFn enc = nullptr;
    cudaDriverEntryPointQueryResult qres;
    cudaGetDriverEntryPoint("cuTensorMapEncodeTiled", (void**)&enc,
                            cudaEnableDefault, &qres);

    CUtensorMap mA{}, mW{};
    {
        cuuint64_t dims[3]    = {64, 128, 512};
        cuuint64_t strides[2] = {128, 128ull * 128};
        cuuint32_t box[3]     = {64, 1, 64};
        cuuint32_t es[3]      = {1, 1, 1};
        enc(&mA, CU_TENSOR_MAP_DATA_TYPE_FLOAT16, 3, xhi, dims, strides, box, es,
            CU_TENSOR_MAP_INTERLEAVE_NONE, CU_TENSOR_MAP_SWIZZLE_128B,
            CU_TENSOR_MAP_L2_PROMOTION_L2_128B, CU_TENSOR_MAP_FLOAT_OOB_FILL_NONE);
    }
    {
        cuuint64_t dims[2]    = {256, 256ull * 64};
        cuuint64_t strides[1] = {512};
        cuuint32_t box[2]     = {64, 64};
        cuuint32_t es[2]      = {1, 1};
        enc(&mW, CU_TENSOR_MAP_DATA_TYPE_FLOAT16, 2, whi, dims, strides, box, es,
            CU_TENSOR_MAP_INTERLEAVE_NONE, CU_TENSOR_MAP_SWIZZLE_128B,
            CU_TENSOR_MAP_L2_PROMOTION_L2_128B, CU_TENSOR_MAP_FLOAT_OOB_FILL_NONE);
    }

    dim3 grid(asl::B_SZ / asl::BM, asl::H_OUT);   // (8, 256)
    asl::gemm_kernel<<<grid, asl::THREADS>>>(mA, mW, mask32, bias, out);
}